// round 3
// baseline (speedup 1.0000x reference)
#include <cuda_runtime.h>

#define NODES_MAX 50000
#define F 128

// Scratch (no runtime allocation allowed)
__device__ float g_P[NODES_MAX * F];       // h @ W1h^T + b1
__device__ float g_sums[NODES_MAX * F];    // segment sums of leaky acts
__device__ float g_T[NODES_MAX * F];       // h @ W2a^T + b2
__device__ float g_counts[NODES_MAX];      // in-degree
__device__ float g_W1T[F * F];             // [k][c] = W1[c*131 + k]
__device__ float g_W2aT[F * F];            // [k][c] = W2[c*256 + k]        (k<128)
__device__ float g_W2bT[F * F];            // [k][c] = W2[c*256 + 128 + k]

// ---------------------------------------------------------------------------
// Prep: transpose weights, zero accumulators
// ---------------------------------------------------------------------------
__global__ void prep_kernel(const float* __restrict__ W1,
                            const float* __restrict__ W2,
                            int n_nodes)
{
    int idx = blockIdx.x * blockDim.x + threadIdx.x;
    int stride = gridDim.x * blockDim.x;

    for (int i = idx; i < F * F; i += stride) {
        int c = i >> 7, k = i & 127;
        g_W1T[k * F + c]  = W1[c * 131 + k];
        g_W2aT[k * F + c] = W2[c * 256 + k];
        g_W2bT[k * F + c] = W2[c * 256 + 128 + k];
    }
    int nsum4 = (n_nodes * F) >> 2;
    float4* s4 = reinterpret_cast<float4*>(g_sums);
    float4 z = make_float4(0.f, 0.f, 0.f, 0.f);
    for (int i = idx; i < nsum4; i += stride) s4[i] = z;
    for (int i = idx; i < n_nodes; i += stride) g_counts[i] = 0.f;
}

// ---------------------------------------------------------------------------
// Core GEMM tile: C[row0:row0+128][0:128] from A (Mx128, row-major, optional
// per-row scale = 1/max(count,1)) times Bt (128x128, [k][c] layout).
// Epilogue: either +bias (per col) store, or +T then relu store.
// 256 threads, 8x8 micro-tile, BK=8, reg-prefetch pipeline.
// ---------------------------------------------------------------------------
template<bool SCALE_A, bool ADD_T_RELU>
__device__ __forceinline__ void gemm_tile(
    const float* __restrict__ A, const float* __restrict__ Bt,
    const float* __restrict__ bias, const float* __restrict__ Tadd,
    float* __restrict__ out, int M, int row0)
{
    __shared__ float As[8][132];   // [k][m], padded
    __shared__ float Bs[8][128];   // [k][c]

    const int tid = threadIdx.x;
    const int tx = tid & 15;       // col quad selector
    const int ty = tid >> 4;       // row quad selector

    // A loader: one float4/thread per tile
    const int lm = tid >> 1;             // 0..127 (row within tile)
    const int lk = (tid & 1) * 4;        // 0 or 4
    const int grow = row0 + lm;
    const bool arow_ok = (grow < M);

    float scale = 1.0f;
    if (SCALE_A)
        scale = arow_ok ? (1.0f / fmaxf(g_counts[grow], 1.0f)) : 0.0f;

    // B loader: one float4/thread per tile
    const int bk = tid >> 5;             // 0..7
    const int bc = (tid & 31) * 4;

    float4 ra = make_float4(0.f, 0.f, 0.f, 0.f);
    if (arow_ok) ra = *(const float4*)(A + grow * 128 + lk);
    float4 rb = *(const float4*)(Bt + bk * 128 + bc);

    float acc[8][8];
    #pragma unroll
    for (int i = 0; i < 8; i++)
        #pragma unroll
        for (int j = 0; j < 8; j++) acc[i][j] = 0.f;

    #pragma unroll 2
    for (int k0 = 0; k0 < 128; k0 += 8) {
        if (SCALE_A) {
            As[lk + 0][lm] = ra.x * scale;
            As[lk + 1][lm] = ra.y * scale;
            As[lk + 2][lm] = ra.z * scale;
            As[lk + 3][lm] = ra.w * scale;
        } else {
            As[lk + 0][lm] = ra.x;
            As[lk + 1][lm] = ra.y;
            As[lk + 2][lm] = ra.z;
            As[lk + 3][lm] = ra.w;
        }
        *(float4*)&Bs[bk][bc] = rb;
        __syncthreads();

        if (k0 + 8 < 128) {   // prefetch next tile into regs
            ra = make_float4(0.f, 0.f, 0.f, 0.f);
            if (arow_ok) ra = *(const float4*)(A + grow * 128 + k0 + 8 + lk);
            rb = *(const float4*)(Bt + (k0 + 8 + bk) * 128 + bc);   // FIXED: + bk
        }

        #pragma unroll
        for (int k = 0; k < 8; k++) {
            float a[8], b[8];
            *(float4*)&a[0] = *(const float4*)&As[k][ty * 4];
            *(float4*)&a[4] = *(const float4*)&As[k][64 + ty * 4];
            *(float4*)&b[0] = *(const float4*)&Bs[k][tx * 4];
            *(float4*)&b[4] = *(const float4*)&Bs[k][64 + tx * 4];
            #pragma unroll
            for (int i = 0; i < 8; i++)
                #pragma unroll
                for (int j = 0; j < 8; j++)
                    acc[i][j] = fmaf(a[i], b[j], acc[i][j]);
        }
        __syncthreads();
    }

    const int c0 = tx * 4;
    const int c1 = 64 + tx * 4;

    float4 bias0, bias1;
    if (!ADD_T_RELU) {
        bias0 = *(const float4*)(bias + c0);
        bias1 = *(const float4*)(bias + c1);
    }

    #pragma unroll
    for (int i = 0; i < 8; i++) {
        int gr = row0 + ((i < 4) ? (ty * 4 + i) : (64 + ty * 4 + i - 4));
        if (gr >= M) continue;
        float4 v0 = make_float4(acc[i][0], acc[i][1], acc[i][2], acc[i][3]);
        float4 v1 = make_float4(acc[i][4], acc[i][5], acc[i][6], acc[i][7]);
        if (ADD_T_RELU) {
            float4 t0 = *(const float4*)(Tadd + gr * 128 + c0);
            float4 t1 = *(const float4*)(Tadd + gr * 128 + c1);
            v0.x = fmaxf(v0.x + t0.x, 0.f); v0.y = fmaxf(v0.y + t0.y, 0.f);
            v0.z = fmaxf(v0.z + t0.z, 0.f); v0.w = fmaxf(v0.w + t0.w, 0.f);
            v1.x = fmaxf(v1.x + t1.x, 0.f); v1.y = fmaxf(v1.y + t1.y, 0.f);
            v1.z = fmaxf(v1.z + t1.z, 0.f); v1.w = fmaxf(v1.w + t1.w, 0.f);
        } else {
            v0.x += bias0.x; v0.y += bias0.y; v0.z += bias0.z; v0.w += bias0.w;
            v1.x += bias1.x; v1.y += bias1.y; v1.z += bias1.z; v1.w += bias1.w;
        }
        *(float4*)(out + gr * 128 + c0) = v0;
        *(float4*)(out + gr * 128 + c1) = v1;
    }
}

// ---------------------------------------------------------------------------
// GEMM1: g_P = h @ W1h^T + b1
// ---------------------------------------------------------------------------
__global__ __launch_bounds__(256) void gemm1_kernel(
    const float* __restrict__ h, const float* __restrict__ b1, int M)
{
    gemm_tile<false, false>(h, g_W1T, b1, nullptr, g_P, M, blockIdx.x * 128);
}

// ---------------------------------------------------------------------------
// Fused: every 4th block computes g_T = h @ W2a^T + b2 (FMA-bound),
// the rest do the edge scatter phase (L2-bound). They overlap.
// ---------------------------------------------------------------------------
__global__ __launch_bounds__(256) void fused_T_edge_kernel(
    const float* __restrict__ h, const float* __restrict__ b2,
    const int* __restrict__ src, const int* __restrict__ dst,
    const float* __restrict__ ew, const float* __restrict__ W1,
    int M, int E, int nT)
{
    const int bid = blockIdx.x;

    if ((bid & 3) == 0) {
        // ---- T-GEMM block ----
        gemm_tile<false, false>(h, g_W2aT, b2, nullptr, g_T, M, (bid >> 2) * 128);
        return;
    }

    // ---- edge block ----
    __shared__ float cw[3][128];
    for (int i = threadIdx.x; i < 384; i += 256) {
        int t = i >> 7, j = i & 127;
        cw[t][j] = W1[j * 131 + 128 + t];
    }
    __syncthreads();

    const int lane = threadIdx.x & 31;
    const int col  = lane * 4;
    const float4 cA = *(const float4*)&cw[0][col];
    const float4 cB = *(const float4*)&cw[1][col];
    const float4 cC = *(const float4*)&cw[2][col];

    const int ebid   = bid - (bid >> 2) - 1;
    const int nEB    = gridDim.x - nT;
    const int gwarp  = ebid * 8 + (threadIdx.x >> 5);
    const int nwarps = nEB * 8;

    for (int e0 = gwarp; e0 < E; e0 += nwarps * 4) {
        int   se[4], de[4];
        float w0[4], w1[4], w2[4];
        float4 p[4];
        bool  v[4];

        #pragma unroll
        for (int u = 0; u < 4; u++) {
            int e = e0 + u * nwarps;
            v[u] = (e < E);
            if (v[u]) {
                se[u] = src[e];
                de[u] = dst[e];
                w0[u] = ew[e * 3 + 0];
                w1[u] = ew[e * 3 + 1];
                w2[u] = ew[e * 3 + 2];
            }
        }
        #pragma unroll
        for (int u = 0; u < 4; u++)
            if (v[u]) p[u] = *(const float4*)(g_P + (long)se[u] * 128 + col);

        #pragma unroll
        for (int u = 0; u < 4; u++) {
            if (!v[u]) continue;
            float t0 = p[u].x + w0[u] * cA.x + w1[u] * cB.x + w2[u] * cC.x;
            float t1 = p[u].y + w0[u] * cA.y + w1[u] * cB.y + w2[u] * cC.y;
            float t2 = p[u].z + w0[u] * cA.z + w1[u] * cB.z + w2[u] * cC.z;
            float t3 = p[u].w + w0[u] * cA.w + w1[u] * cB.w + w2[u] * cC.w;
            t0 = (t0 < 0.f) ? 0.01f * t0 : t0;
            t1 = (t1 < 0.f) ? 0.01f * t1 : t1;
            t2 = (t2 < 0.f) ? 0.01f * t2 : t2;
            t3 = (t3 < 0.f) ? 0.01f * t3 : t3;
            float* addr = g_sums + (long)de[u] * 128 + col;
            asm volatile("red.global.add.v4.f32 [%0], {%1, %2, %3, %4};"
                         :: "l"(addr), "f"(t0), "f"(t1), "f"(t2), "f"(t3)
                         : "memory");
            if (lane == 0) atomicAdd(&g_counts[de[u]], 1.0f);
        }
    }
}

// ---------------------------------------------------------------------------
// GEMM3: out = relu( (g_sums * inv_count) @ W2b^T + g_T )
// ---------------------------------------------------------------------------
__global__ __launch_bounds__(256) void gemm3_kernel(float* __restrict__ out, int M)
{
    gemm_tile<true, true>(g_sums, g_W2bT, nullptr, g_T, out, M, blockIdx.x * 128);
}

// ---------------------------------------------------------------------------
extern "C" void kernel_launch(void* const* d_in, const int* in_sizes, int n_in,
                              void* d_out, int out_size)
{
    const float* h    = (const float*)d_in[0];
    const int*   esrc = (const int*)  d_in[1];
    const int*   edst = (const int*)  d_in[2];
    const float* ew   = (const float*)d_in[3];
    const float* W1   = (const float*)d_in[4];
    const float* b1   = (const float*)d_in[5];
    const float* W2   = (const float*)d_in[6];
    const float* b2   = (const float*)d_in[7];
    float* out = (float*)d_out;

    int M = in_sizes[0] / 128;   // 50000 nodes
    int E = in_sizes[1];         // 800000 edges
    int nT = (M + 127) / 128;    // 391 gemm tiles

    prep_kernel<<<256, 256>>>(W1, W2, M);
    gemm1_kernel<<<nT, 256>>>(h, b1, M);
    fused_T_edge_kernel<<<nT * 4, 256>>>(h, b2, esrc, edst, ew, W1, M, E, nT);
    gemm3_kernel<<<nT, 256>>>(out, M);
}

// round 4
// speedup vs baseline: 1.1414x; 1.1414x over previous
#include <cuda_runtime.h>

#define NODES_MAX 50000
#define F 128

// Scratch (no runtime allocation allowed)
__device__ float g_P[NODES_MAX * F];       // h @ W1h^T + b1
__device__ float g_sums[NODES_MAX * F];    // segment sums of leaky acts
__device__ float g_T[NODES_MAX * F];       // h @ W2a^T + b2
__device__ float g_counts[NODES_MAX];      // in-degree
__device__ float g_W1T[F * F];             // [k][c] = W1[c*131 + k]
__device__ float g_W2aT[F * F];            // [k][c] = W2[c*256 + k]        (k<128)
__device__ float g_W2bT[F * F];            // [k][c] = W2[c*256 + 128 + k]

// ---------------------------------------------------------------------------
// Prep: transpose weights, zero accumulators
// ---------------------------------------------------------------------------
__global__ void prep_kernel(const float* __restrict__ W1,
                            const float* __restrict__ W2,
                            int n_nodes)
{
    int idx = blockIdx.x * blockDim.x + threadIdx.x;
    int stride = gridDim.x * blockDim.x;

    for (int i = idx; i < F * F; i += stride) {
        int c = i >> 7, k = i & 127;
        g_W1T[k * F + c]  = W1[c * 131 + k];
        g_W2aT[k * F + c] = W2[c * 256 + k];
        g_W2bT[k * F + c] = W2[c * 256 + 128 + k];
    }
    int nsum4 = (n_nodes * F) >> 2;
    float4* s4 = reinterpret_cast<float4*>(g_sums);
    float4 z = make_float4(0.f, 0.f, 0.f, 0.f);
    for (int i = idx; i < nsum4; i += stride) s4[i] = z;
    for (int i = idx; i < n_nodes; i += stride) g_counts[i] = 0.f;
}

// ---------------------------------------------------------------------------
// Core GEMM tile with packed f32x2 FMAs (FFMA2): C[row0+128][128] =
// A(Mx128, optional per-row 1/max(count,1) scale) x Bt(128x128, [k][c]).
// 256 threads, 8x8 micro-tile, BK=8, register-prefetch pipeline.
// ---------------------------------------------------------------------------
template<bool SCALE_A, bool ADD_T_RELU>
__device__ __forceinline__ void gemm_tile(
    const float* __restrict__ A, const float* __restrict__ Bt,
    const float* __restrict__ bias, const float* __restrict__ Tadd,
    float* __restrict__ out, int M, int row0)
{
    __shared__ float As[8][132];   // [k][m], padded
    __shared__ float Bs[8][128];   // [k][c]

    const int tid = threadIdx.x;
    const int tx = tid & 15;       // col quad selector
    const int ty = tid >> 4;       // row quad selector

    const int lm = tid >> 1;             // 0..127 (row within tile)
    const int lk = (tid & 1) * 4;        // 0 or 4
    const int grow = row0 + lm;
    const bool arow_ok = (grow < M);

    float scale = 1.0f;
    if (SCALE_A)
        scale = arow_ok ? (1.0f / fmaxf(g_counts[grow], 1.0f)) : 0.0f;

    const int bk = tid >> 5;             // 0..7
    const int bc = (tid & 31) * 4;

    float4 ra = make_float4(0.f, 0.f, 0.f, 0.f);
    if (arow_ok) ra = *(const float4*)(A + grow * 128 + lk);
    float4 rb = *(const float4*)(Bt + bk * 128 + bc);

    // Packed accumulators: acc[i][j] = cols {c+2j, c+2j+1} (j<2 lower half,
    // j>=2 upper half at +64)
    unsigned long long acc[8][4];
    #pragma unroll
    for (int i = 0; i < 8; i++)
        #pragma unroll
        for (int j = 0; j < 4; j++) acc[i][j] = 0ull;

    #pragma unroll 2
    for (int k0 = 0; k0 < 128; k0 += 8) {
        if (SCALE_A) {
            As[lk + 0][lm] = ra.x * scale;
            As[lk + 1][lm] = ra.y * scale;
            As[lk + 2][lm] = ra.z * scale;
            As[lk + 3][lm] = ra.w * scale;
        } else {
            As[lk + 0][lm] = ra.x;
            As[lk + 1][lm] = ra.y;
            As[lk + 2][lm] = ra.z;
            As[lk + 3][lm] = ra.w;
        }
        *(float4*)&Bs[bk][bc] = rb;
        __syncthreads();

        if (k0 + 8 < 128) {   // prefetch next tile into regs
            ra = make_float4(0.f, 0.f, 0.f, 0.f);
            if (arow_ok) ra = *(const float4*)(A + grow * 128 + k0 + 8 + lk);
            rb = *(const float4*)(Bt + (k0 + 8 + bk) * 128 + bc);
        }

        #pragma unroll
        for (int k = 0; k < 8; k++) {
            float a[8];
            *(float4*)&a[0] = *(const float4*)&As[k][ty * 4];
            *(float4*)&a[4] = *(const float4*)&As[k][64 + ty * 4];
            unsigned long long bp[4];
            {
                double2 d0 = *(const double2*)&Bs[k][tx * 4];
                double2 d1 = *(const double2*)&Bs[k][64 + tx * 4];
                bp[0] = __double_as_longlong(d0.x);
                bp[1] = __double_as_longlong(d0.y);
                bp[2] = __double_as_longlong(d1.x);
                bp[3] = __double_as_longlong(d1.y);
            }
            #pragma unroll
            for (int i = 0; i < 8; i++) {
                unsigned long long ad;
                asm("mov.b64 %0, {%1, %2};" : "=l"(ad) : "f"(a[i]), "f"(a[i]));
                #pragma unroll
                for (int j = 0; j < 4; j++)
                    asm("fma.rn.f32x2 %0, %1, %2, %0;"
                        : "+l"(acc[i][j]) : "l"(ad), "l"(bp[j]));
            }
        }
        __syncthreads();
    }

    const int c0 = tx * 4;
    const int c1 = 64 + tx * 4;

    float4 bias0, bias1;
    if (!ADD_T_RELU) {
        bias0 = *(const float4*)(bias + c0);
        bias1 = *(const float4*)(bias + c1);
    }

    #pragma unroll
    for (int i = 0; i < 8; i++) {
        int gr = row0 + ((i < 4) ? (ty * 4 + i) : (64 + ty * 4 + i - 4));
        if (gr >= M) continue;
        float4 v0, v1;
        asm("mov.b64 {%0, %1}, %2;" : "=f"(v0.x), "=f"(v0.y) : "l"(acc[i][0]));
        asm("mov.b64 {%0, %1}, %2;" : "=f"(v0.z), "=f"(v0.w) : "l"(acc[i][1]));
        asm("mov.b64 {%0, %1}, %2;" : "=f"(v1.x), "=f"(v1.y) : "l"(acc[i][2]));
        asm("mov.b64 {%0, %1}, %2;" : "=f"(v1.z), "=f"(v1.w) : "l"(acc[i][3]));
        if (ADD_T_RELU) {
            float4 t0 = *(const float4*)(Tadd + gr * 128 + c0);
            float4 t1 = *(const float4*)(Tadd + gr * 128 + c1);
            v0.x = fmaxf(v0.x + t0.x, 0.f); v0.y = fmaxf(v0.y + t0.y, 0.f);
            v0.z = fmaxf(v0.z + t0.z, 0.f); v0.w = fmaxf(v0.w + t0.w, 0.f);
            v1.x = fmaxf(v1.x + t1.x, 0.f); v1.y = fmaxf(v1.y + t1.y, 0.f);
            v1.z = fmaxf(v1.z + t1.z, 0.f); v1.w = fmaxf(v1.w + t1.w, 0.f);
        } else {
            v0.x += bias0.x; v0.y += bias0.y; v0.z += bias0.z; v0.w += bias0.w;
            v1.x += bias1.x; v1.y += bias1.y; v1.z += bias1.z; v1.w += bias1.w;
        }
        *(float4*)(out + gr * 128 + c0) = v0;
        *(float4*)(out + gr * 128 + c1) = v1;
    }
}

// ---------------------------------------------------------------------------
// Dual GEMM: bid < nT computes g_P = h @ W1h^T + b1,
//            bid >= nT computes g_T = h @ W2a^T + b2.
// Uniform register class, one launch = better wave packing.
// ---------------------------------------------------------------------------
__global__ __launch_bounds__(256) void gemm_dual_kernel(
    const float* __restrict__ h, const float* __restrict__ b1,
    const float* __restrict__ b2, int M, int nT)
{
    int bid = blockIdx.x;
    if (bid < nT)
        gemm_tile<false, false>(h, g_W1T, b1, nullptr, g_P, M, bid * 128);
    else
        gemm_tile<false, false>(h, g_W2aT, b2, nullptr, g_T, M, (bid - nT) * 128);
}

// ---------------------------------------------------------------------------
// Edge kernel (standalone, low-reg, high occupancy): one warp per edge,
// x4 unrolled grid-stride to keep >=4 gathers in flight per warp.
// ---------------------------------------------------------------------------
__global__ __launch_bounds__(256) void edge_kernel(
    const int* __restrict__ src, const int* __restrict__ dst,
    const float* __restrict__ ew, const float* __restrict__ W1, int E)
{
    __shared__ float cw[3][128];
    for (int i = threadIdx.x; i < 384; i += 256) {
        int t = i >> 7, j = i & 127;
        cw[t][j] = W1[j * 131 + 128 + t];
    }
    __syncthreads();

    const int lane = threadIdx.x & 31;
    const int col  = lane * 4;
    const float4 cA = *(const float4*)&cw[0][col];
    const float4 cB = *(const float4*)&cw[1][col];
    const float4 cC = *(const float4*)&cw[2][col];

    const int gwarp  = (blockIdx.x * 256 + threadIdx.x) >> 5;
    const int nwarps = (gridDim.x * 256) >> 5;

    for (int e0 = gwarp; e0 < E; e0 += nwarps * 4) {
        int   se[4], de[4];
        float w0[4], w1[4], w2[4];
        float4 p[4];
        bool  v[4];

        #pragma unroll
        for (int u = 0; u < 4; u++) {
            int e = e0 + u * nwarps;
            v[u] = (e < E);
            if (v[u]) {
                se[u] = src[e];
                de[u] = dst[e];
                w0[u] = ew[e * 3 + 0];
                w1[u] = ew[e * 3 + 1];
                w2[u] = ew[e * 3 + 2];
            }
        }
        #pragma unroll
        for (int u = 0; u < 4; u++)
            if (v[u]) p[u] = *(const float4*)(g_P + (long)se[u] * 128 + col);

        #pragma unroll
        for (int u = 0; u < 4; u++) {
            if (!v[u]) continue;
            float t0 = p[u].x + w0[u] * cA.x + w1[u] * cB.x + w2[u] * cC.x;
            float t1 = p[u].y + w0[u] * cA.y + w1[u] * cB.y + w2[u] * cC.y;
            float t2 = p[u].z + w0[u] * cA.z + w1[u] * cB.z + w2[u] * cC.z;
            float t3 = p[u].w + w0[u] * cA.w + w1[u] * cB.w + w2[u] * cC.w;
            t0 = (t0 < 0.f) ? 0.01f * t0 : t0;
            t1 = (t1 < 0.f) ? 0.01f * t1 : t1;
            t2 = (t2 < 0.f) ? 0.01f * t2 : t2;
            t3 = (t3 < 0.f) ? 0.01f * t3 : t3;
            float* addr = g_sums + (long)de[u] * 128 + col;
            asm volatile("red.global.add.v4.f32 [%0], {%1, %2, %3, %4};"
                         :: "l"(addr), "f"(t0), "f"(t1), "f"(t2), "f"(t3)
                         : "memory");
            if (lane == 0) atomicAdd(&g_counts[de[u]], 1.0f);
        }
    }
}

// ---------------------------------------------------------------------------
// GEMM3: out = relu( (g_sums * inv_count) @ W2b^T + g_T )
// ---------------------------------------------------------------------------
__global__ __launch_bounds__(256) void gemm3_kernel(float* __restrict__ out, int M)
{
    gemm_tile<true, true>(g_sums, g_W2bT, nullptr, g_T, out, M, blockIdx.x * 128);
}

// ---------------------------------------------------------------------------
extern "C" void kernel_launch(void* const* d_in, const int* in_sizes, int n_in,
                              void* d_out, int out_size)
{
    const float* h    = (const float*)d_in[0];
    const int*   esrc = (const int*)  d_in[1];
    const int*   edst = (const int*)  d_in[2];
    const float* ew   = (const float*)d_in[3];
    const float* W1   = (const float*)d_in[4];
    const float* b1   = (const float*)d_in[5];
    const float* W2   = (const float*)d_in[6];
    const float* b2   = (const float*)d_in[7];
    float* out = (float*)d_out;

    int M = in_sizes[0] / 128;   // 50000 nodes
    int E = in_sizes[1];         // 800000 edges
    int nT = (M + 127) / 128;    // 391 gemm tiles

    prep_kernel<<<512, 256>>>(W1, W2, M);
    gemm_dual_kernel<<<nT * 2, 256>>>(h, b1, b2, M, nT);
    edge_kernel<<<1480, 256>>>(esrc, edst, ew, W1, E);
    gemm3_kernel<<<nT, 256>>>(out, M);
}